// round 4
// baseline (speedup 1.0000x reference)
#include <cuda_runtime.h>
#include <math.h>

#define Bb 2
#define Hh 48
#define Ww 48
#define Cc 192
#define NH 8
#define Nn 2304            // Hh*Ww
#define QW 4               // queries per warp
#define NWARPS 16          // 512 threads
#define QT (QW*NWARPS)     // 64 queries per block
#define NTILES (Nn/QT)     // 36
// SCALE * log2(e): fold softmax scale and exp->ex2 conversion into q & bias
#define SL2E 0.5100420914154871f

// smem: skA,skB,svA,svB: 4 * 2304 * 16B = 147456
//       sph, spw: 2 * 16 warps * 48 pos * 16B = 24576
#define SMEM_BYTES (Nn*4*16 + 2*NWARPS*48*16)

typedef unsigned long long ull;

__device__ __forceinline__ ull pk2(float lo, float hi) {
    ull r; asm("mov.b64 %0,{%1,%2};" : "=l"(r) : "f"(lo), "f"(hi)); return r;
}
__device__ __forceinline__ void upk2(ull v, float& lo, float& hi) {
    asm("mov.b64 {%0,%1},%2;" : "=f"(lo), "=f"(hi) : "l"(v));
}
__device__ __forceinline__ ull fma2(ull a, ull b, ull c) {
    ull d; asm("fma.rn.f32x2 %0,%1,%2,%3;" : "=l"(d) : "l"(a), "l"(b), "l"(c)); return d;
}
__device__ __forceinline__ ull add2(ull a, ull b) {
    ull d; asm("add.rn.f32x2 %0,%1,%2;" : "=l"(d) : "l"(a), "l"(b)); return d;
}
__device__ __forceinline__ ull mul2(ull a, ull b) {
    ull d; asm("mul.rn.f32x2 %0,%1,%2;" : "=l"(d) : "l"(a), "l"(b)); return d;
}
__device__ __forceinline__ float ex2f(float x) {
    float r; asm("ex2.approx.f32 %0,%1;" : "=f"(r) : "f"(x)); return r;
}

__global__ __launch_bounds__(512, 1)
void attn_aug2d_kernel(const float* __restrict__ inp,
                       const float* __restrict__ relw,
                       const float* __restrict__ relh,
                       float* __restrict__ out)
{
    extern __shared__ float smem[];
    ulonglong2* skA = (ulonglong2*)smem;   // [Nn] k dims 0..3
    ulonglong2* skB = skA + Nn;            // [Nn] k dims 4..7
    ulonglong2* svA = skB + Nn;            // [Nn] v dims 0..3
    ulonglong2* svB = svA + Nn;            // [Nn] v dims 4..7
    ulonglong2* sph = svB + Nn;            // [NWARPS][48] (4 floats each)
    ulonglong2* spw = sph + NWARPS*48;     // [NWARPS][48]

    const int tid  = threadIdx.x;
    const int warp = tid >> 5;
    const int lane = tid & 31;
    const int tile = blockIdx.x;
    const int h    = blockIdx.y;
    const int b    = blockIdx.z;

    // ---- stage K, V into smem ----
    for (int m = tid; m < Nn; m += 512) {
        const float* base = inp + ((size_t)(b*Nn + m))*Cc + 64 + h*8; // k channels
        skA[m] = *(const ulonglong2*)(base);
        skB[m] = *(const ulonglong2*)(base + 4);
        svA[m] = *(const ulonglong2*)(base + 64);  // v = k + 64 channels
        svB[m] = *(const ulonglong2*)(base + 68);
    }

    // ---- per-warp separable bias tables (pre-scaled by SCALE*log2e) ----
    const int q0 = tile*QT + warp*QW;
    for (int e = lane; e < 2*48*QW; e += 32) {
        int t   = e / (48*QW);         // 0 = ph, 1 = pw
        int rem = e - t*(48*QW);
        int pos = rem >> 2;
        int qi  = rem & 3;
        int n   = q0 + qi;
        int x   = n / 48;
        int y   = n - x*48;
        const float* qptr = inp + ((size_t)(b*Nn + n))*Cc + h*8;
        const float* rel  = (t == 0) ? (relh + (pos - x + 47)*8)
                                     : (relw + (pos - y + 47)*8);
        float s = 0.f;
        #pragma unroll
        for (int d = 0; d < 8; d++) s += qptr[d]*rel[d];
        float* dst = (float*)((t == 0) ? sph : spw);
        dst[(warp*48 + pos)*4 + qi] = s * SL2E;
    }
    __syncthreads();

    // ---- queries packed over dims: qXp[p] = (q_2p, q_2p+1) * SL2E ----
    ull q0p[4], q1p[4], q2p[4], q3p[4];
    {
        const ull sl2 = pk2(SL2E, SL2E);
        #pragma unroll
        for (int i = 0; i < QW; i++) {
            const float* qptr = inp + ((size_t)(b*Nn + q0 + i))*Cc + h*8;
            ulonglong2 a = *(const ulonglong2*)(qptr);
            ulonglong2 c = *(const ulonglong2*)(qptr + 4);
            ull* dst = (i==0)?q0p:(i==1)?q1p:(i==2)?q2p:q3p;
            dst[0] = mul2(a.x, sl2);
            dst[1] = mul2(a.y, sl2);
            dst[2] = mul2(c.x, sl2);
            dst[3] = mul2(c.y, sl2);
        }
    }

    ull acc0[4], acc1[4], acc2[4], acc3[4];
    #pragma unroll
    for (int p = 0; p < 4; p++) { acc0[p]=0; acc1[p]=0; acc2[p]=0; acc3[p]=0; }
    float s0=0.f, s1=0.f, s2=0.f, s3=0.f;

    const ulonglong2* php = sph + warp*48;   // ph[X], X starts at 0 (lane < 48)
    const ulonglong2* pww = spw + warp*48;
    int m = lane;
    int r = lane;                            // r = Y = key - 48*X

    // prologue: prefetch first k
    ulonglong2 kA = skA[m], kB = skB[m];

    #pragma unroll 6
    for (int it = 0; it < Nn/32; it++) {
        // loads whose latency is hidden by the dot/ex2 chain below
        ulonglong2 vA = svA[m], vB = svB[m];
        ulonglong2 ph = *php;
        ulonglong2 pw = pww[r];
        // prefetch NEXT iteration's k (overrun on last iter lands in skB; discarded)
        ulonglong2 nkA = skA[m + 32], nkB = skB[m + 32];

        // dots on current (pre-loaded) k — starts immediately, no LDS wait
        ull d0 = mul2(q0p[0], kA.x);
        ull d1 = mul2(q1p[0], kA.x);
        ull d2 = mul2(q2p[0], kA.x);
        ull d3 = mul2(q3p[0], kA.x);
        d0 = fma2(q0p[1], kA.y, d0); d1 = fma2(q1p[1], kA.y, d1);
        d2 = fma2(q2p[1], kA.y, d2); d3 = fma2(q3p[1], kA.y, d3);
        d0 = fma2(q0p[2], kB.x, d0); d1 = fma2(q1p[2], kB.x, d1);
        d2 = fma2(q2p[2], kB.x, d2); d3 = fma2(q3p[2], kB.x, d3);
        d0 = fma2(q0p[3], kB.y, d0); d1 = fma2(q1p[3], kB.y, d1);
        d2 = fma2(q2p[3], kB.y, d2); d3 = fma2(q3p[3], kB.y, d3);

        ull pp01 = add2(ph.x, pw.x);
        ull pp23 = add2(ph.y, pw.y);

        float b0,b1,b2,b3, lo,hi;
        upk2(pp01, b0, b1); upk2(pp23, b2, b3);
        upk2(d0, lo, hi); float w0 = ex2f(lo + hi + b0);
        upk2(d1, lo, hi); float w1 = ex2f(lo + hi + b1);
        upk2(d2, lo, hi); float w2 = ex2f(lo + hi + b2);
        upk2(d3, lo, hi); float w3 = ex2f(lo + hi + b3);

        s0 += w0; s1 += w1; s2 += w2; s3 += w3;

        ull wd;
        wd = pk2(w0,w0);
        acc0[0]=fma2(wd,vA.x,acc0[0]); acc0[1]=fma2(wd,vA.y,acc0[1]);
        acc0[2]=fma2(wd,vB.x,acc0[2]); acc0[3]=fma2(wd,vB.y,acc0[3]);
        wd = pk2(w1,w1);
        acc1[0]=fma2(wd,vA.x,acc1[0]); acc1[1]=fma2(wd,vA.y,acc1[1]);
        acc1[2]=fma2(wd,vB.x,acc1[2]); acc1[3]=fma2(wd,vB.y,acc1[3]);
        wd = pk2(w2,w2);
        acc2[0]=fma2(wd,vA.x,acc2[0]); acc2[1]=fma2(wd,vA.y,acc2[1]);
        acc2[2]=fma2(wd,vB.x,acc2[2]); acc2[3]=fma2(wd,vB.y,acc2[3]);
        wd = pk2(w3,w3);
        acc3[0]=fma2(wd,vA.x,acc3[0]); acc3[1]=fma2(wd,vA.y,acc3[1]);
        acc3[2]=fma2(wd,vB.x,acc3[2]); acc3[3]=fma2(wd,vB.y,acc3[3]);

        kA = nkA; kB = nkB;
        m += 32;
        r += 32;
        if (r >= 48) { r -= 48; php++; }
    }

    // ---- warp reduction (packed accs + scalar sums) ----
    #pragma unroll
    for (int o = 16; o > 0; o >>= 1) {
        s0 += __shfl_xor_sync(0xffffffffu, s0, o);
        s1 += __shfl_xor_sync(0xffffffffu, s1, o);
        s2 += __shfl_xor_sync(0xffffffffu, s2, o);
        s3 += __shfl_xor_sync(0xffffffffu, s3, o);
        #pragma unroll
        for (int p = 0; p < 4; p++) {
            acc0[p] = add2(acc0[p], __shfl_xor_sync(0xffffffffu, acc0[p], o));
            acc1[p] = add2(acc1[p], __shfl_xor_sync(0xffffffffu, acc1[p], o));
            acc2[p] = add2(acc2[p], __shfl_xor_sync(0xffffffffu, acc2[p], o));
            acc3[p] = add2(acc3[p], __shfl_xor_sync(0xffffffffu, acc3[p], o));
        }
    }

    if (lane == 0) {
        float r0 = 1.0f/s0, r1 = 1.0f/s1, r2 = 1.0f/s2, r3 = 1.0f/s3;
        ull rd;
        ulonglong2 oA, oB;
        size_t obase = ((size_t)(b*Nn + q0))*64 + h*8;

        rd = pk2(r0,r0);
        oA.x = mul2(acc0[0],rd); oA.y = mul2(acc0[1],rd);
        oB.x = mul2(acc0[2],rd); oB.y = mul2(acc0[3],rd);
        *(ulonglong2*)(out + obase)      = oA;
        *(ulonglong2*)(out + obase + 4)  = oB;

        rd = pk2(r1,r1);
        oA.x = mul2(acc1[0],rd); oA.y = mul2(acc1[1],rd);
        oB.x = mul2(acc1[2],rd); oB.y = mul2(acc1[3],rd);
        *(ulonglong2*)(out + obase + 64)     = oA;
        *(ulonglong2*)(out + obase + 64 + 4) = oB;

        rd = pk2(r2,r2);
        oA.x = mul2(acc2[0],rd); oA.y = mul2(acc2[1],rd);
        oB.x = mul2(acc2[2],rd); oB.y = mul2(acc2[3],rd);
        *(ulonglong2*)(out + obase + 128)     = oA;
        *(ulonglong2*)(out + obase + 128 + 4) = oB;

        rd = pk2(r3,r3);
        oA.x = mul2(acc3[0],rd); oA.y = mul2(acc3[1],rd);
        oB.x = mul2(acc3[2],rd); oB.y = mul2(acc3[3],rd);
        *(ulonglong2*)(out + obase + 192)     = oA;
        *(ulonglong2*)(out + obase + 192 + 4) = oB;
    }
}

extern "C" void kernel_launch(void* const* d_in, const int* in_sizes, int n_in,
                              void* d_out, int out_size)
{
    const float* inp  = (const float*)d_in[0];
    const float* relw = (const float*)d_in[1];
    const float* relh = (const float*)d_in[2];
    float* out = (float*)d_out;

    cudaFuncSetAttribute(attn_aug2d_kernel,
                         cudaFuncAttributeMaxDynamicSharedMemorySize, SMEM_BYTES);
    dim3 grid(NTILES, NH, Bb);
    attn_aug2d_kernel<<<grid, 512, SMEM_BYTES>>>(inp, relw, relh, out);
}